// round 16
// baseline (speedup 1.0000x reference)
#include <cuda_runtime.h>

// Gaussian splatting via tile-owned gather (8x8x16 tiles), precomputed
// per-gaussian exp tables.
//  K0 (memset): zero per-tile counters.
//  K1 fused tables+scatter: one thread per table slot (112 per gaussian)
//     builds padded exp tables (coalesced STG); slots 0..17 additionally
//     scatter the gaussian into overlapped tile buckets (<=1 atomic each).
//     Tables per gaussian: x[32] y[32] z[48]; x/y anchored mn-8, z anchored
//     mn-16; zeros outside bbox; intensity folded into z.
//  K2 accum: 64-thread CTA per tile, warps split x (4-wide slabs); thread
//     (yi, zq) owns 4x * 4z voxels as 8 f32x2 accumulators. Warp-uniform
//     skip of all-zero x-slabs; branchless packed f32x2 FMAs otherwise.
//     Writeout: 4 STG.128 per thread, 8 lines per warp op (no transpose).

#define NTILES 16384                   // 32 x 32 x 16
#define CAP 64
#define NMAX 65536
#define TABW 112

__device__ int  d_counts[NTILES];
__device__ int2 d_bucket[NTILES * CAP];   // {offpack, gid*TABW}
__device__ float d_gtab[NMAX * TABW];

__device__ __forceinline__ void fma2(unsigned long long& d,
                                     unsigned long long a,
                                     unsigned long long b) {
    asm("fma.rn.f32x2 %0, %1, %2, %0;" : "+l"(d) : "l"(a), "l"(b));
}
__device__ __forceinline__ unsigned long long mul2(unsigned long long a,
                                                   unsigned long long b) {
    unsigned long long r;
    asm("mul.rn.f32x2 %0, %1, %2;" : "=l"(r) : "l"(a), "l"(b));
    return r;
}
__device__ __forceinline__ unsigned long long dup2(float x) {
    unsigned long long r;
    asm("mov.b64 %0, {%1, %1};" : "=l"(r) : "f"(x));
    return r;
}
__device__ __forceinline__ float2 unpack2(unsigned long long v) {
    float2 r;
    asm("mov.b64 {%0, %1}, %2;" : "=f"(r.x), "=f"(r.y) : "l"(v));
    return r;
}

// Shared bbox computation (identical arithmetic everywhere -> identical boxes).
__device__ __forceinline__ void bbox_axis(float c, float cut, int& mn, int& mx) {
    float cv = c * 255.0f;
    mn = (int)floorf(fmaxf(cv - cut, 0.0f));
    mx = (int)fminf(floorf(fminf(cv + cut, 255.0f)) + 1.0f, 256.0f);
}

// One thread per table slot (112 per gaussian); slots 0..17 also scatter.
__global__ void __launch_bounds__(256) table_scatter_kernel(
        const float* __restrict__ centers,
        const float* __restrict__ sigmas,
        const float* __restrict__ intensities,
        int n) {
    int e = blockIdx.x * blockDim.x + threadIdx.x;
    int g = e / TABW;
    if (g >= n) return;
    int s = e - g * TABW;

    const float sig    = __ldg(&sigmas[g]);
    const float cut    = 3.0f * sig * 255.0f;
    const float inv2s2 = 0.5f / (sig * sig);

    // --- table entry ---
    {
        int a   = (s < 32) ? 0 : ((s < 64) ? 1 : 2);
        int i   = s - ((a == 0) ? 0 : ((a == 1) ? 32 : 64));
        int pad = (a == 2) ? 16 : 8;

        const float c = __ldg(&centers[3 * g + a]);
        int mn_a, mx_a;
        bbox_axis(c, cut, mn_a, mx_a);
        int w_a = mx_a - mn_a;

        float v = 0.0f;
        if ((unsigned)(i - pad) < (unsigned)w_a) {
            float d = (float)(mn_a - pad + i) * (1.0f / 255.0f) - c;
            v = __expf(-d * d * inv2s2);
            if (a == 2) v *= __ldg(&intensities[g]);
        }
        d_gtab[e] = v;
    }

    // --- scatter (slots 0..17 -> (dx, dy, dz) in 3x3x2) ---
    if (s < 18) {
        int dz = s & 1;
        int q  = s >> 1;
        int dx = q / 3;
        int dy = q - dx * 3;

        int mnx, mxx, mny, mxy, mnz, mxz;
        bbox_axis(__ldg(&centers[3 * g + 0]), cut, mnx, mxx);
        bbox_axis(__ldg(&centers[3 * g + 1]), cut, mny, mxy);
        bbox_axis(__ldg(&centers[3 * g + 2]), cut, mnz, mxz);

        int t0x = mnx >> 3, nx = ((mxx - 1) >> 3) - t0x;
        int t0y = mny >> 3, ny = ((mxy - 1) >> 3) - t0y;
        int t0z = mnz >> 4, nz = ((mxz - 1) >> 4) - t0z;

        if (dx <= nx && dy <= ny && dz <= nz) {
            int tx = t0x + dx, ty = t0y + dy, tz = t0z + dz;
            int t = (tx << 9) | (ty << 4) | tz;
            int offx = (tx << 3) - mnx + 8;
            int offy = (ty << 3) - mny + 8 + 32;
            int offz = (tz << 4) - mnz + 16 + 64;
            int pack = offx | (offy << 8) | (offz << 16);
            int slot = atomicAdd(&d_counts[t], 1);
            if (slot < CAP) d_bucket[t * CAP + slot] = make_int2(pack, g * TABW);
        }
    }
}

__global__ void __launch_bounds__(64) accum_kernel(float* __restrict__ out) {
    const int t    = blockIdx.x;
    const int tid  = threadIdx.x;
    const int wid  = tid >> 5;        // warp -> x slab [4*wid, 4*wid+4)
    const int lane = tid & 31;
    const int ox = (t >> 9) << 3;
    const int oy = ((t >> 4) & 31) << 3;
    const int oz = (t & 15) << 4;

    __shared__ int2 sbk[CAP];
    __shared__ __align__(16) float sx[CAP * 8];
    __shared__ __align__(16) float sy[CAP * 8];
    __shared__ __align__(16) float sz[CAP * 16];

    int cnt = d_counts[t];
    if (cnt > CAP) cnt = CAP;
    const int bucket_base = t * CAP;

    for (int i = tid; i < cnt; i += 64)
        sbk[i] = d_bucket[bucket_base + i];
    __syncthreads();

    // Window gathers (tile-ready offsets from scatter; always in-range).
    const int n8 = cnt * 8;
    for (int e = tid; e < n8; e += 64) {
        int g = e >> 3, i = e & 7;
        int2 bk = sbk[g];
        sx[e] = d_gtab[bk.y + (bk.x & 255) + i];
    }
    for (int e = tid; e < n8; e += 64) {
        int g = e >> 3, i = e & 7;
        int2 bk = sbk[g];
        sy[e] = d_gtab[bk.y + ((bk.x >> 8) & 255) + i];
    }
    const int n16 = cnt * 16;
    for (int e = tid; e < n16; e += 64) {
        int g = e >> 4, i = e & 15;
        int2 bk = sbk[g];
        sz[e] = d_gtab[bk.y + ((bk.x >> 16) & 255) + i];
    }
    __syncthreads();

    const int yi = lane >> 2;         // 0..7
    const int zq = lane & 3;          // 0..3 (z quarter)
    const float* syp = &sy[yi];
    const float* szp = &sz[4 * zq];
    const float* sxp = &sx[4 * wid];

    // Thread owns voxels (x in slab, y = yi, z in [4zq, 4zq+4)).
    unsigned long long accL[4], accH[4];
#pragma unroll
    for (int x = 0; x < 4; x++) { accL[x] = 0ULL; accH[x] = 0ULL; }

#pragma unroll 2
    for (int g = 0; g < cnt; g++) {
        float4 xv = *(const float4*)&sxp[g * 8];
        // Warp-uniform skip: all table entries >= 0; sum==0 <=> slab inactive.
        float sm = (xv.x + xv.y) + (xv.z + xv.w);
        if (sm == 0.0f) continue;

        float syv = syp[g * 8];
        ulonglong2 zz = *(const ulonglong2*)&szp[g * 16];
        unsigned long long syd = dup2(syv);
        unsigned long long t0 = mul2(syd, zz.x);   // sy * (z0, z1)
        unsigned long long t1 = mul2(syd, zz.y);   // sy * (z2, z3)
        unsigned long long w;
        w = dup2(xv.x); fma2(accL[0], w, t0); fma2(accH[0], w, t1);
        w = dup2(xv.y); fma2(accL[1], w, t0); fma2(accH[1], w, t1);
        w = dup2(xv.z); fma2(accL[2], w, t0); fma2(accH[2], w, t1);
        w = dup2(xv.w); fma2(accL[3], w, t0); fma2(accH[3], w, t1);
    }

    // Writeout: per x, warp op covers one x-slab (8 y-rows x 64B) = 8 lines.
    const int addr0 = (ox + 4 * wid) * 65536 + (oy + yi) * 256 + oz + 4 * zq;
#pragma unroll
    for (int x = 0; x < 4; x++) {
        float2 lo = unpack2(accL[x]);
        float2 hi = unpack2(accH[x]);
        *(float4*)&out[addr0 + x * 65536] = make_float4(lo.x, lo.y, hi.x, hi.y);
    }
}

extern "C" void kernel_launch(void* const* d_in, const int* in_sizes, int n_in,
                              void* d_out, int out_size) {
    const float* centers = (const float*)d_in[0];
    const float* sigmas = (const float*)d_in[1];
    const float* intensities = (const float*)d_in[2];
    float* out = (float*)d_out;
    const int n = in_sizes[1];

    void* counts_ptr = nullptr;
    cudaGetSymbolAddress(&counts_ptr, d_counts);
    cudaMemsetAsync(counts_ptr, 0, NTILES * sizeof(int), 0);

    table_scatter_kernel<<<(n * TABW + 255) / 256, 256>>>(centers, sigmas, intensities, n);
    accum_kernel<<<NTILES, 64>>>(out);
}